// round 8
// baseline (speedup 1.0000x reference)
#include <cuda_runtime.h>
#include <cstdint>

// Fixed problem shape: num_pos = 8192, num = 4000, N_TOT = 32,776,192.
#define POS_CAP   8192          // rows (num_pos)
#define WORDS_CAP (POS_CAP / 2) // u16-packed counter words
#define NBLK      592           // passB: 148 SMs * 4 blocks (48KB smem each)
#define NBLKA     1184          // passA: 148 SMs * 8 blocks
#define PB_THREADS 256

__device__ float        g_pos[POS_CAP];                   // pos[j] values (32KB)
__device__ int          g_cnt[POS_CAP];                   // final per-row counts
__device__ unsigned int g_part[(size_t)NBLK * WORDS_CAP]; // per-block tiles (9.7MB)
__device__ float        g_sum;                            // mrr accumulator
__device__ unsigned int g_tick;                           // finalize ticket

// ---------------------------------------------------------------------------
// Pass A: stream index (int32), grid-stride, 4x int4 per iteration (MLP=4).
// Where j < num_pos, fetch val[i] into pos[j]. Also zero counters/accums.
__global__ void __launch_bounds__(256)
passA_kernel(const float* __restrict__ val,
             const int4* __restrict__ idx4,
             long long n4, long long n_tot, int num_pos) {
    long long tid0 = (long long)blockIdx.x * blockDim.x + threadIdx.x;

    if (tid0 < num_pos) g_cnt[tid0] = 0;
    if (tid0 == 0) { g_sum = 0.0f; g_tick = 0u; }

    const long long nthreads = (long long)gridDim.x * blockDim.x;

    #define SCAT(II, BASE)                                                     \
    {                                                                          \
        if ((unsigned)(II).x < (unsigned)num_pos) g_pos[(II).x] = val[(BASE)];     \
        if ((unsigned)(II).y < (unsigned)num_pos) g_pos[(II).y] = val[(BASE) + 1]; \
        if ((unsigned)(II).z < (unsigned)num_pos) g_pos[(II).z] = val[(BASE) + 2]; \
        if ((unsigned)(II).w < (unsigned)num_pos) g_pos[(II).w] = val[(BASE) + 3]; \
    }

    // Main: 4 int4 loads in flight per iteration.
    long long n4_main = n4 & ~3LL;  // groups of 4 int4s
    for (long long g = tid0 * 4; g + 3 < n4; g += nthreads * 4) {
        int4 a = __ldcs(&idx4[g]);
        int4 b = __ldcs(&idx4[g + 1]);
        int4 c = __ldcs(&idx4[g + 2]);
        int4 d = __ldcs(&idx4[g + 3]);
        SCAT(a, 4 * g)
        SCAT(b, 4 * (g + 1))
        SCAT(c, 4 * (g + 2))
        SCAT(d, 4 * (g + 3))
    }
    // Remainder int4s.
    for (long long t = (n4_main / 4) * 4 + tid0; t < n4; t += nthreads) {
        int4 a = __ldcs(&idx4[t]);
        SCAT(a, 4 * t)
    }
    #undef SCAT

    // Scalar tail (not hit for this shape).
    if (tid0 == 0) {
        const int* idx = (const int*)idx4;
        for (long long i = 4 * n4; i < n_tot; i++) {
            int j = idx[i];
            if ((unsigned)j < (unsigned)num_pos) g_pos[j] = val[i];
        }
    }
}

// ---------------------------------------------------------------------------
// Pass B: stream val+idx. Negatives: p = (j - num_pos) * M >> 42 (magic div
// by num). Compare vs smem pos cache, count into u16-packed SMEM counters
// (ATOMS), then dump the block's tile with plain coalesced stores.
__global__ void __launch_bounds__(PB_THREADS)
passB_kernel(const float4* __restrict__ val4,
             const int4* __restrict__ idx4,
             long long n4, long long n_tot,
             int num_pos, unsigned long long M) {
    __shared__ float        s_pos[POS_CAP];   // 32KB
    __shared__ unsigned int s_cnt[WORDS_CAP]; // 16KB (2 x u16 rows per word)

    int words = (num_pos + 1) >> 1;
    for (int k = threadIdx.x; k < num_pos; k += blockDim.x)
        s_pos[k] = g_pos[k];
    for (int k = threadIdx.x; k < words; k += blockDim.x)
        s_cnt[k] = 0u;
    __syncthreads();

    long long stride = (long long)gridDim.x * blockDim.x;
    for (long long t = (long long)blockIdx.x * blockDim.x + threadIdx.x;
         t < n4; t += stride) {
        float4 v = val4[t];
        int4  ii = idx4[t];

        #define PROC(JJ, VV)                                                  \
        {                                                                     \
            if ((JJ) >= num_pos) {                                            \
                unsigned d = (unsigned)((JJ) - num_pos);                      \
                unsigned p = (unsigned)(((unsigned long long)d * M) >> 42);   \
                if ((VV) > s_pos[p])                                          \
                    atomicAdd(&s_cnt[p >> 1], 1u << ((p & 1u) << 4));         \
            }                                                                 \
        }
        PROC(ii.x, v.x)
        PROC(ii.y, v.y)
        PROC(ii.z, v.z)
        PROC(ii.w, v.w)
        #undef PROC
    }

    // Scalar tail (not hit for this shape).
    if (blockIdx.x == 0 && threadIdx.x == 0) {
        const float* val = (const float*)val4;
        const int*   idx = (const int*)idx4;
        for (long long i = 4 * n4; i < n_tot; i++) {
            int j = idx[i];
            if (j >= num_pos) {
                unsigned p = (unsigned)(((unsigned long long)(j - num_pos) * M) >> 42);
                if (val[i] > s_pos[p])
                    atomicAdd(&s_cnt[p >> 1], 1u << ((p & 1u) << 4));
            }
        }
    }
    __syncthreads();

    // Dump tile: plain coalesced stores, no atomics.
    size_t base = (size_t)blockIdx.x * words;
    for (int w = threadIdx.x; w < words; w += blockDim.x)
        g_part[base + w] = s_cnt[w];
}

// ---------------------------------------------------------------------------
// Reduce: sum NBLK tiles into g_cnt. RED_CH chunks per word; tiles L2-hot.
#define RED_CH 8
__global__ void reduce_kernel(int words, int nblk, int num_pos) {
    int tid = blockIdx.x * blockDim.x + threadIdx.x;
    int total = words * RED_CH;
    if (tid >= total) return;
    int w = tid % words;
    int c = tid / words;
    int per = (nblk + RED_CH - 1) / RED_CH;
    int b0 = c * per;
    int b1 = b0 + per; if (b1 > nblk) b1 = nblk;

    unsigned lo = 0, hi = 0;
    for (int b = b0; b < b1; b++) {
        unsigned x = g_part[(size_t)b * words + w];
        lo += x & 0xFFFFu;
        hi += x >> 16;
    }
    atomicAdd(&g_cnt[2 * w], (int)lo);
    if (2 * w + 1 < num_pos) atomicAdd(&g_cnt[2 * w + 1], (int)hi);
}

// ---------------------------------------------------------------------------
// Finalize: multi-block. smrr = 1/(1+cnt) -> out[1+i]; block partial sums ->
// atomicAdd(g_sum); last block (ticket) writes out[0] = mean.
__global__ void finalize_kernel(float* __restrict__ out, int num_pos) {
    __shared__ float s_warp[32];
    int nthreads = gridDim.x * blockDim.x;
    float local = 0.0f;
    for (int i = blockIdx.x * blockDim.x + threadIdx.x; i < num_pos; i += nthreads) {
        float smrr = 1.0f / (float)(1 + g_cnt[i]);
        out[1 + i] = smrr;
        local += smrr;
    }
    for (int o = 16; o > 0; o >>= 1)
        local += __shfl_xor_sync(0xFFFFFFFFu, local, o);
    int lane = threadIdx.x & 31, wid = threadIdx.x >> 5;
    if (lane == 0) s_warp[wid] = local;
    __syncthreads();
    if (wid == 0) {
        int nw = (blockDim.x + 31) >> 5;
        float s = (lane < nw) ? s_warp[lane] : 0.0f;
        for (int o = 16; o > 0; o >>= 1)
            s += __shfl_xor_sync(0xFFFFFFFFu, s, o);
        if (lane == 0) {
            atomicAdd(&g_sum, s);
            __threadfence();
            unsigned t = atomicAdd(&g_tick, 1u);
            if (t == gridDim.x - 1) {
                out[0] = g_sum / (float)num_pos;
            }
        }
    }
}

// ---------------------------------------------------------------------------
extern "C" void kernel_launch(void* const* d_in, const int* in_sizes, int n_in,
                              void* d_out, int out_size) {
    const float* val = (const float*)d_in[0];
    const int*   idx = (const int*)d_in[1];   // int32 (JAX x64 disabled)
    float* out = (float*)d_out;

    long long n_tot = (long long)in_sizes[0];

    int num_pos = out_size - 1;               // out = [mrr, sample_mrr(num_pos)]
    if (num_pos < 1) num_pos = 1;
    if (num_pos > POS_CAP) num_pos = POS_CAP;
    long long num_ll = n_tot / num_pos - 1;
    unsigned num = (num_ll > 0) ? (unsigned)num_ll : 1u;

    // Magic for division by num: p = (d * M) >> 42, exact for this range.
    unsigned long long M = (4398046511104ULL / num) + 1ULL;  // 2^42

    long long n4 = n_tot / 4;
    int words = (num_pos + 1) >> 1;

    // Pass A: grid-stride, deep MLP
    passA_kernel<<<NBLKA, 256>>>(val, (const int4*)idx, n4, n_tot, num_pos);

    // Pass B: fixed grid (4 blocks/SM), smem counters, no global atomics
    passB_kernel<<<NBLK, PB_THREADS>>>((const float4*)val, (const int4*)idx,
                                       n4, n_tot, num_pos, M);

    // Reduce tiles
    {
        int total = words * RED_CH;
        reduce_kernel<<<(total + 255) / 256, 256>>>(words, NBLK, num_pos);
    }

    // Finalize: 32 blocks, last-block writes the mean
    finalize_kernel<<<32, 256>>>(out, num_pos);
}

// round 10
// speedup vs baseline: 1.3764x; 1.3764x over previous
#include <cuda_runtime.h>
#include <cstdint>

// Fixed problem shape: num_pos = 8192, num = 4000, N_TOT = 32,776,192.
#define POS_CAP   8192          // rows (num_pos)
#define WORDS_CAP (POS_CAP / 2) // u16-packed counter words
#define NBLK      592           // passB: 148 SMs * 4 blocks (48KB smem each)
#define NBLKA     1184          // passA: 148 SMs * 8 blocks
#define PB_THREADS 256
#define RED_CH    8

__device__ float        g_pos[POS_CAP];                   // pos[j] values (32KB)
__device__ int          g_cnt[POS_CAP];                   // final per-row counts
__device__ unsigned int g_part[(size_t)NBLK * WORDS_CAP]; // per-block tiles (9.7MB)
__device__ float        g_sum;                            // mrr accumulator
__device__ unsigned int g_tick;                           // fused-tail ticket

// ---------------------------------------------------------------------------
// Pass A: stream index (int32). Grid-stride with stride-nthreads unroll x4:
// every LDG is fully coalesced (lane-consecutive int4s) and 4 independent
// loads are in flight per thread. Where j < num_pos, fetch val[i] -> pos[j].
// Also zeroes g_cnt / g_sum / g_tick for this replay.
__global__ void __launch_bounds__(256)
passA_kernel(const float* __restrict__ val,
             const int4* __restrict__ idx4,
             long long n4, long long n_tot, int num_pos) {
    long long tid0 = (long long)blockIdx.x * blockDim.x + threadIdx.x;

    if (tid0 < num_pos) g_cnt[tid0] = 0;
    if (tid0 == 0) { g_sum = 0.0f; g_tick = 0u; }

    const long long nthreads = (long long)gridDim.x * blockDim.x;

    #define SCAT(II, BASE)                                                         \
    {                                                                              \
        if ((unsigned)(II).x < (unsigned)num_pos) g_pos[(II).x] = val[(BASE)];     \
        if ((unsigned)(II).y < (unsigned)num_pos) g_pos[(II).y] = val[(BASE) + 1]; \
        if ((unsigned)(II).z < (unsigned)num_pos) g_pos[(II).z] = val[(BASE) + 2]; \
        if ((unsigned)(II).w < (unsigned)num_pos) g_pos[(II).w] = val[(BASE) + 3]; \
    }

    for (long long base = tid0; base < n4; base += 4 * nthreads) {
        long long t0 = base;
        long long t1 = base + nthreads;
        long long t2 = base + 2 * nthreads;
        long long t3 = base + 3 * nthreads;
        // Independent, coalesced loads (predicated at the ragged end).
        int4 a = idx4[t0];                                   // t0 < n4 guaranteed
        int4 b = (t1 < n4) ? idx4[t1] : make_int4(-1,-1,-1,-1);
        int4 c = (t2 < n4) ? idx4[t2] : make_int4(-1,-1,-1,-1);
        int4 d = (t3 < n4) ? idx4[t3] : make_int4(-1,-1,-1,-1);
        SCAT(a, 4 * t0)
        SCAT(b, 4 * t1)
        SCAT(c, 4 * t2)
        SCAT(d, 4 * t3)
    }
    #undef SCAT

    // Scalar tail (not hit for this shape).
    if (tid0 == 0) {
        const int* idx = (const int*)idx4;
        for (long long i = 4 * n4; i < n_tot; i++) {
            int j = idx[i];
            if ((unsigned)j < (unsigned)num_pos) g_pos[j] = val[i];
        }
    }
}

// ---------------------------------------------------------------------------
// Pass B: stream val+idx. Negatives: p = (j - num_pos) * M >> 42 (magic div
// by num). Compare vs smem pos cache, count into u16-packed SMEM counters
// (ATOMS), then dump the block's tile with plain coalesced stores.
// (Unchanged from the 96.7us version.)
__global__ void __launch_bounds__(PB_THREADS)
passB_kernel(const float4* __restrict__ val4,
             const int4* __restrict__ idx4,
             long long n4, long long n_tot,
             int num_pos, unsigned long long M) {
    __shared__ float        s_pos[POS_CAP];   // 32KB
    __shared__ unsigned int s_cnt[WORDS_CAP]; // 16KB (2 x u16 rows per word)

    int words = (num_pos + 1) >> 1;
    for (int k = threadIdx.x; k < num_pos; k += blockDim.x)
        s_pos[k] = g_pos[k];
    for (int k = threadIdx.x; k < words; k += blockDim.x)
        s_cnt[k] = 0u;
    __syncthreads();

    long long stride = (long long)gridDim.x * blockDim.x;
    for (long long t = (long long)blockIdx.x * blockDim.x + threadIdx.x;
         t < n4; t += stride) {
        float4 v = val4[t];
        int4  ii = idx4[t];

        #define PROC(JJ, VV)                                                  \
        {                                                                     \
            if ((JJ) >= num_pos) {                                            \
                unsigned d = (unsigned)((JJ) - num_pos);                      \
                unsigned p = (unsigned)(((unsigned long long)d * M) >> 42);   \
                if ((VV) > s_pos[p])                                          \
                    atomicAdd(&s_cnt[p >> 1], 1u << ((p & 1u) << 4));         \
            }                                                                 \
        }
        PROC(ii.x, v.x)
        PROC(ii.y, v.y)
        PROC(ii.z, v.z)
        PROC(ii.w, v.w)
        #undef PROC
    }

    // Scalar tail (not hit for this shape).
    if (blockIdx.x == 0 && threadIdx.x == 0) {
        const float* val = (const float*)val4;
        const int*   idx = (const int*)idx4;
        for (long long i = 4 * n4; i < n_tot; i++) {
            int j = idx[i];
            if (j >= num_pos) {
                unsigned p = (unsigned)(((unsigned long long)(j - num_pos) * M) >> 42);
                if (val[i] > s_pos[p])
                    atomicAdd(&s_cnt[p >> 1], 1u << ((p & 1u) << 4));
            }
        }
    }
    __syncthreads();

    // Dump tile: plain coalesced stores, no atomics.
    size_t base = (size_t)blockIdx.x * words;
    for (int w = threadIdx.x; w < words; w += blockDim.x)
        g_part[base + w] = s_cnt[w];
}

// ---------------------------------------------------------------------------
// Fused reduce + finalize. Phase 1: each thread folds its tile-chunk into
// g_cnt (atomics; tiles are L2-hot). Phase 2: last block (ticket) computes
// smrr for all rows, writes out[1..], and out[0] = mean.
__global__ void __launch_bounds__(256)
tail_kernel(float* __restrict__ out, int words, int nblk, int num_pos) {
    __shared__ float s_warp[32];

    // Phase 1: tile reduction
    int tid = blockIdx.x * blockDim.x + threadIdx.x;
    int total = words * RED_CH;
    if (tid < total) {
        int w = tid % words;
        int c = tid / words;
        int per = (nblk + RED_CH - 1) / RED_CH;
        int b0 = c * per;
        int b1 = b0 + per; if (b1 > nblk) b1 = nblk;

        unsigned lo = 0, hi = 0;
        for (int b = b0; b < b1; b++) {
            unsigned x = g_part[(size_t)b * words + w];
            lo += x & 0xFFFFu;
            hi += x >> 16;
        }
        atomicAdd(&g_cnt[2 * w], (int)lo);
        if (2 * w + 1 < num_pos) atomicAdd(&g_cnt[2 * w + 1], (int)hi);
    }

    // Ticket: last block to finish phase 1 runs phase 2.
    __threadfence();
    __syncthreads();
    __shared__ unsigned s_is_last;
    if (threadIdx.x == 0)
        s_is_last = (atomicAdd(&g_tick, 1u) == gridDim.x - 1) ? 1u : 0u;
    __syncthreads();
    if (!s_is_last) return;

    // Phase 2: smrr + mean (one block, g_cnt is L2-hot)
    float local = 0.0f;
    for (int i = threadIdx.x; i < num_pos; i += blockDim.x) {
        float smrr = 1.0f / (float)(1 + g_cnt[i]);
        out[1 + i] = smrr;
        local += smrr;
    }
    for (int o = 16; o > 0; o >>= 1)
        local += __shfl_xor_sync(0xFFFFFFFFu, local, o);
    int lane = threadIdx.x & 31, wid = threadIdx.x >> 5;
    if (lane == 0) s_warp[wid] = local;
    __syncthreads();
    if (wid == 0) {
        int nw = (blockDim.x + 31) >> 5;
        float s = (lane < nw) ? s_warp[lane] : 0.0f;
        for (int o = 16; o > 0; o >>= 1)
            s += __shfl_xor_sync(0xFFFFFFFFu, s, o);
        if (lane == 0) out[0] = s / (float)num_pos;
    }
}

// ---------------------------------------------------------------------------
extern "C" void kernel_launch(void* const* d_in, const int* in_sizes, int n_in,
                              void* d_out, int out_size) {
    const float* val = (const float*)d_in[0];
    const int*   idx = (const int*)d_in[1];   // int32 (JAX x64 disabled)
    float* out = (float*)d_out;

    long long n_tot = (long long)in_sizes[0];

    int num_pos = out_size - 1;               // out = [mrr, sample_mrr(num_pos)]
    if (num_pos < 1) num_pos = 1;
    if (num_pos > POS_CAP) num_pos = POS_CAP;
    long long num_ll = n_tot / num_pos - 1;
    unsigned num = (num_ll > 0) ? (unsigned)num_ll : 1u;

    // Magic for division by num: p = (d * M) >> 42, exact for this range.
    unsigned long long M = (4398046511104ULL / num) + 1ULL;  // 2^42

    long long n4 = n_tot / 4;
    int words = (num_pos + 1) >> 1;

    // Pass A: grid-stride, strided unroll x4 (coalesced + MLP=4)
    passA_kernel<<<NBLKA, 256>>>(val, (const int4*)idx, n4, n_tot, num_pos);

    // Pass B: fixed grid (4 blocks/SM), smem counters, no global atomics
    passB_kernel<<<NBLK, PB_THREADS>>>((const float4*)val, (const int4*)idx,
                                       n4, n_tot, num_pos, M);

    // Fused reduce + finalize (ticket: last block writes smrr + mean)
    {
        int total = words * RED_CH;
        int blocks = (total + 255) / 256;
        tail_kernel<<<blocks, 256>>>(out, words, NBLK, num_pos);
    }
}

// round 13
// speedup vs baseline: 1.4394x; 1.0457x over previous
#include <cuda_runtime.h>
#include <cstdint>

// Fixed problem shape: num_pos = 8192, num = 4000, N_TOT = 32,776,192.
#define POS_CAP   8192          // rows (num_pos)
#define WORDS_CAP (POS_CAP / 2) // u16-packed counter words
#define NBLK      592           // passB: 148 SMs * 4 blocks (48KB smem each)
#define NBLKA     1184          // passA: 148 SMs * 8 blocks
#define PB_THREADS 256
#define RED_CH    8

__device__ float        g_pos[POS_CAP];                   // pos[j] values (32KB)
__device__ int          g_cnt[POS_CAP];                   // final per-row counts
__device__ unsigned int g_part[(size_t)NBLK * WORDS_CAP]; // per-block tiles (9.7MB)

// ---------------------------------------------------------------------------
// Pass A: stream index (int32). Grid-stride, stride-nthreads unroll x4:
// every LDG fully coalesced, 4 independent loads in flight per thread.
// Default cache policy so idx lines stay in L2 for passB's reverse read.
__global__ void __launch_bounds__(256)
passA_kernel(const float* __restrict__ val,
             const int4* __restrict__ idx4,
             long long n4, long long n_tot, int num_pos) {
    long long tid0 = (long long)blockIdx.x * blockDim.x + threadIdx.x;

    if (tid0 < num_pos) g_cnt[tid0] = 0;

    const long long nthreads = (long long)gridDim.x * blockDim.x;

    #define SCAT(II, BASE)                                                         \
    {                                                                              \
        if ((unsigned)(II).x < (unsigned)num_pos) g_pos[(II).x] = val[(BASE)];     \
        if ((unsigned)(II).y < (unsigned)num_pos) g_pos[(II).y] = val[(BASE) + 1]; \
        if ((unsigned)(II).z < (unsigned)num_pos) g_pos[(II).z] = val[(BASE) + 2]; \
        if ((unsigned)(II).w < (unsigned)num_pos) g_pos[(II).w] = val[(BASE) + 3]; \
    }

    for (long long base = tid0; base < n4; base += 4 * nthreads) {
        long long t0 = base;
        long long t1 = base + nthreads;
        long long t2 = base + 2 * nthreads;
        long long t3 = base + 3 * nthreads;
        int4 a = idx4[t0];
        int4 b = (t1 < n4) ? idx4[t1] : make_int4(-1,-1,-1,-1);
        int4 c = (t2 < n4) ? idx4[t2] : make_int4(-1,-1,-1,-1);
        int4 d = (t3 < n4) ? idx4[t3] : make_int4(-1,-1,-1,-1);
        SCAT(a, 4 * t0)
        SCAT(b, 4 * t1)
        SCAT(c, 4 * t2)
        SCAT(d, 4 * t3)
    }
    #undef SCAT

    // Scalar tail (not hit for this shape).
    if (tid0 == 0) {
        const int* idx = (const int*)idx4;
        for (long long i = 4 * n4; i < n_tot; i++) {
            int j = idx[i];
            if ((unsigned)j < (unsigned)num_pos) g_pos[j] = val[i];
        }
    }
}

// ---------------------------------------------------------------------------
// Pass B: stream val+idx IN REVERSE (tail of idx is L2-resident after passA).
// val uses __ldcs (evict-first) to avoid evicting the retained idx lines.
// Negatives: p = (j - num_pos) * M >> 42 (magic div by num). Compare vs smem
// pos cache, count into u16-packed SMEM counters, dump tile coalesced.
__global__ void __launch_bounds__(PB_THREADS)
passB_kernel(const float4* __restrict__ val4,
             const int4* __restrict__ idx4,
             long long n4, long long n_tot,
             int num_pos, unsigned long long M) {
    __shared__ float        s_pos[POS_CAP];   // 32KB
    __shared__ unsigned int s_cnt[WORDS_CAP]; // 16KB (2 x u16 rows per word)

    int words = (num_pos + 1) >> 1;
    for (int k = threadIdx.x; k < num_pos; k += blockDim.x)
        s_pos[k] = g_pos[k];
    for (int k = threadIdx.x; k < words; k += blockDim.x)
        s_cnt[k] = 0u;
    __syncthreads();

    long long stride = (long long)gridDim.x * blockDim.x;
    for (long long r = (long long)blockIdx.x * blockDim.x + threadIdx.x;
         r < n4; r += stride) {
        long long t = n4 - 1 - r;          // reverse traversal
        float4 v;
        { const float4* p4 = &val4[t];
          v.x = __ldcs(&((const float*)p4)[0]);
          v.y = __ldcs(&((const float*)p4)[1]);
          v.z = __ldcs(&((const float*)p4)[2]);
          v.w = __ldcs(&((const float*)p4)[3]); }
        int4 ii = idx4[t];

        #define PROC(JJ, VV)                                                  \
        {                                                                     \
            if ((JJ) >= num_pos) {                                            \
                unsigned d = (unsigned)((JJ) - num_pos);                      \
                unsigned p = (unsigned)(((unsigned long long)d * M) >> 42);   \
                if ((VV) > s_pos[p])                                          \
                    atomicAdd(&s_cnt[p >> 1], 1u << ((p & 1u) << 4));         \
            }                                                                 \
        }
        PROC(ii.x, v.x)
        PROC(ii.y, v.y)
        PROC(ii.z, v.z)
        PROC(ii.w, v.w)
        #undef PROC
    }

    // Scalar tail (not hit for this shape).
    if (blockIdx.x == 0 && threadIdx.x == 0) {
        const float* val = (const float*)val4;
        const int*   idx = (const int*)idx4;
        for (long long i = 4 * n4; i < n_tot; i++) {
            int j = idx[i];
            if (j >= num_pos) {
                unsigned p = (unsigned)(((unsigned long long)(j - num_pos) * M) >> 42);
                if (val[i] > s_pos[p])
                    atomicAdd(&s_cnt[p >> 1], 1u << ((p & 1u) << 4));
            }
        }
    }
    __syncthreads();

    // Dump tile: plain coalesced stores, no atomics.
    size_t base = (size_t)blockIdx.x * words;
    for (int w = threadIdx.x; w < words; w += blockDim.x)
        g_part[base + w] = s_cnt[w];
}

// ---------------------------------------------------------------------------
// Reduce: sum NBLK tiles into g_cnt. RED_CH chunks per word; tiles L2-hot.
__global__ void reduce_kernel(int words, int nblk, int num_pos) {
    int tid = blockIdx.x * blockDim.x + threadIdx.x;
    int total = words * RED_CH;
    if (tid >= total) return;
    int w = tid % words;
    int c = tid / words;
    int per = (nblk + RED_CH - 1) / RED_CH;
    int b0 = c * per;
    int b1 = b0 + per; if (b1 > nblk) b1 = nblk;

    unsigned lo = 0, hi = 0;
    for (int b = b0; b < b1; b++) {
        unsigned x = g_part[(size_t)b * words + w];
        lo += x & 0xFFFFu;
        hi += x >> 16;
    }
    atomicAdd(&g_cnt[2 * w], (int)lo);
    if (2 * w + 1 < num_pos) atomicAdd(&g_cnt[2 * w + 1], (int)hi);
}

// ---------------------------------------------------------------------------
// Finalize: smrr = 1/(1+cnt), out[0] = mean, out[1..] = smrr. One block.
__global__ void finalize_kernel(float* __restrict__ out, int num_pos) {
    __shared__ float s_warp[32];
    float local = 0.0f;
    for (int i = threadIdx.x; i < num_pos; i += blockDim.x) {
        float smrr = 1.0f / (float)(1 + g_cnt[i]);
        out[1 + i] = smrr;
        local += smrr;
    }
    for (int o = 16; o > 0; o >>= 1)
        local += __shfl_xor_sync(0xFFFFFFFFu, local, o);
    int lane = threadIdx.x & 31, wid = threadIdx.x >> 5;
    if (lane == 0) s_warp[wid] = local;
    __syncthreads();
    if (wid == 0) {
        int nw = (blockDim.x + 31) >> 5;
        float s = (lane < nw) ? s_warp[lane] : 0.0f;
        for (int o = 16; o > 0; o >>= 1)
            s += __shfl_xor_sync(0xFFFFFFFFu, s, o);
        if (lane == 0) out[0] = s / (float)num_pos;
    }
}

// ---------------------------------------------------------------------------
extern "C" void kernel_launch(void* const* d_in, const int* in_sizes, int n_in,
                              void* d_out, int out_size) {
    const float* val = (const float*)d_in[0];
    const int*   idx = (const int*)d_in[1];   // int32 (JAX x64 disabled)
    float* out = (float*)d_out;

    long long n_tot = (long long)in_sizes[0];

    int num_pos = out_size - 1;               // out = [mrr, sample_mrr(num_pos)]
    if (num_pos < 1) num_pos = 1;
    if (num_pos > POS_CAP) num_pos = POS_CAP;
    long long num_ll = n_tot / num_pos - 1;
    unsigned num = (num_ll > 0) ? (unsigned)num_ll : 1u;

    // Magic for division by num: p = (d * M) >> 42, exact for this range.
    unsigned long long M = (4398046511104ULL / num) + 1ULL;  // 2^42

    long long n4 = n_tot / 4;
    int words = (num_pos + 1) >> 1;

    // Pass A: grid-stride, strided unroll x4 (coalesced + MLP=4), L2-retaining
    passA_kernel<<<NBLKA, 256>>>(val, (const int4*)idx, n4, n_tot, num_pos);

    // Pass B: reverse traversal (L2 reuse of idx), smem counters
    passB_kernel<<<NBLK, PB_THREADS>>>((const float4*)val, (const int4*)idx,
                                       n4, n_tot, num_pos, M);

    // Reduce tiles
    {
        int total = words * RED_CH;
        reduce_kernel<<<(total + 255) / 256, 256>>>(words, NBLK, num_pos);
    }

    // Finalize
    finalize_kernel<<<1, 1024>>>(out, num_pos);
}